// round 10
// baseline (speedup 1.0000x reference)
#include <cuda_runtime.h>
#include <cuda_fp16.h>
#include <cstdint>

#define IN_DIM  256
#define OUT_DIM 128
#define B_ROWS  4096
#define N_COLS  8192
#define ALPHA   0.2f
#define NSPLIT  8
#define NCHUNK  (N_COLS / NSPLIT)  // 1024 n per CTA
#define KT      32                 // n per K-tile
#define NT      (NCHUNK / KT)      // 32 tiles

// ---------------- device scratch (static, allocation-free) ----------------
__device__ __align__(16) __half g_hb[N_COLS * OUT_DIM]; // [8192 n][128 f] fp16
__device__ float g_s2[N_COLS];
__device__ float g_p[N_COLS];
__device__ float g_q[N_COLS];
__device__ float g_t[B_ROWS];   // -s1[b]
__device__ float g_P[B_ROWS];
__device__ float g_Q[B_ROWS];
__device__ unsigned int g_s2max_bits;                   // order-mapped float max
__device__ __align__(16) float g_acc[B_ROWS * OUT_DIM]; // RED target, 2 MB

// ---------------- helpers ----------------
__device__ __forceinline__ uint32_t smem_u32(const void* p) {
    uint32_t a;
    asm("{ .reg .u64 t; cvta.to.shared.u64 t, %1; cvt.u32.u64 %0, t; }"
        : "=r"(a) : "l"(p));
    return a;
}
__device__ __forceinline__ void cpa16(uint32_t s, const void* g) {
    asm volatile("cp.async.cg.shared.global [%0], [%1], 16;" :: "r"(s), "l"(g));
}
__device__ __forceinline__ void sts32(uint32_t a, uint32_t v) {
    asm volatile("st.shared.b32 [%0], %1;" :: "r"(a), "r"(v));
}
__device__ __forceinline__ void ldsm4(uint32_t* r, uint32_t a) {
    asm volatile("ldmatrix.sync.aligned.m8n8.x4.shared.b16 {%0,%1,%2,%3}, [%4];"
                 : "=r"(r[0]), "=r"(r[1]), "=r"(r[2]), "=r"(r[3]) : "r"(a));
}
__device__ __forceinline__ void ldsm4t(uint32_t* r, uint32_t a) {
    asm volatile("ldmatrix.sync.aligned.m8n8.x4.trans.shared.b16 {%0,%1,%2,%3}, [%4];"
                 : "=r"(r[0]), "=r"(r[1]), "=r"(r[2]), "=r"(r[3]) : "r"(a));
}
__device__ __forceinline__ void mma_f16(float* d, const uint32_t* a,
                                        uint32_t b0, uint32_t b1) {
    asm volatile(
        "mma.sync.aligned.m16n8k16.row.col.f32.f16.f16.f32 "
        "{%0,%1,%2,%3},{%4,%5,%6,%7},{%8,%9},{%0,%1,%2,%3};"
        : "+f"(d[0]), "+f"(d[1]), "+f"(d[2]), "+f"(d[3])
        : "r"(a[0]), "r"(a[1]), "r"(a[2]), "r"(a[3]), "r"(b0), "r"(b1));
}
__device__ __forceinline__ void redadd(float* p, float v) {
    asm volatile("red.global.add.f32 [%0], %1;" :: "l"(p), "f"(v) : "memory");
}
// order-preserving float <-> uint map (works for negatives)
__device__ __forceinline__ unsigned int f2key(float f) {
    int i = __float_as_int(f);
    return (i >= 0) ? ((unsigned)i ^ 0x80000000u) : ~(unsigned)i;
}
__device__ __forceinline__ float key2f(unsigned int k) {
    int i = (k & 0x80000000u) ? (int)(k ^ 0x80000000u) : (int)~k;
    return __int_as_float(i);
}

// ---------------- K1: k_prep — Wa1 (local), s1 -> g_t, zero g_acc ----------
__global__ __launch_bounds__(256) void k_prep(const float* __restrict__ gf,
                                              const int* __restrict__ nodes,
                                              const float* __restrict__ W,
                                              const float* __restrict__ a1) {
    __shared__ float sWa1[IN_DIM];
    int t = threadIdx.x, lane = t & 31, wid = t >> 5;
    if (blockIdx.x == 0 && t == 0) g_s2max_bits = 0u;  // < key of any finite s2
    // Wa1[k] = W[k,:] . a1
    {
        const float* row = W + t * OUT_DIM;
        float s = 0.f;
#pragma unroll 8
        for (int c = 0; c < OUT_DIM; c++) s += row[c] * a1[c];
        sWa1[t] = s;
    }
    // zero this CTA's slice of g_acc (4096 floats)
    {
        float4 z = make_float4(0.f, 0.f, 0.f, 0.f);
        float* dst = g_acc + (size_t)blockIdx.x * 4096 + t * 16;
#pragma unroll
        for (int k = 0; k < 4; k++) ((float4*)dst)[k] = z;
    }
    __syncthreads();
#pragma unroll
    for (int rr = 0; rr < 4; rr++) {
        int b = blockIdx.x * 32 + wid * 4 + rr;
        const float* row = gf + (size_t)nodes[b] * IN_DIM;
        float s = 0.f;
#pragma unroll
        for (int k = lane; k < IN_DIM; k += 32) s += row[k] * sWa1[k];
#pragma unroll
        for (int o = 16; o; o >>= 1) s += __shfl_xor_sync(0xffffffffu, s, o);
        if (lane == 0) g_t[b] = -s;
    }
}

// ---------------- K2: k_hneigh — pipelined h = gf[un]@W; s2, max ----------
__global__ __launch_bounds__(256) void k_hneigh(
    const float* __restrict__ gf, const int* __restrict__ un,
    const float* __restrict__ W, const float* __restrict__ a2) {
    __shared__ __align__(16) float As[2][32][36];   // gathered gf block
    __shared__ __align__(16) float Ws[2][32][132];  // W k-block
    int t = threadIdx.x, lane = t & 31, wid = t >> 5;
    int r0 = blockIdx.x * 32;

    // cp.async roles
    const int arow = t >> 3, ach = t & 7;          // 32 rows x 8 chunks (gf)
    const float* asrc = gf + (size_t)un[r0 + arow] * IN_DIM + ach * 4;
    uint32_t adst[2] = {smem_u32(&As[0][arow][ach * 4]),
                        smem_u32(&As[1][arow][ach * 4])};
    uint32_t wdst[2][4];
    const float* wsrc[4];
#pragma unroll
    for (int u = 0; u < 4; u++) {
        int idx = t * 4 + u, wrow = idx >> 5, wch = idx & 31;
        wsrc[u] = W + (size_t)wrow * OUT_DIM + wch * 4;
        wdst[0][u] = smem_u32(&Ws[0][wrow][wch * 4]);
        wdst[1][u] = smem_u32(&Ws[1][wrow][wch * 4]);
    }

    // preload block 0
    cpa16(adst[0], asrc);
#pragma unroll
    for (int u = 0; u < 4; u++) cpa16(wdst[0][u], wsrc[u]);
    asm volatile("cp.async.commit_group;");

    float acc[4][4] = {};
    for (int kb = 0; kb < 8; kb++) {
        const int cur = kb & 1;
        if (kb + 1 < 8) {  // prefetch next block into other buffer
            cpa16(adst[cur ^ 1], asrc + (kb + 1) * 32);
#pragma unroll
            for (int u = 0; u < 4; u++)
                cpa16(wdst[cur ^ 1][u], wsrc[u] + (size_t)(kb + 1) * 32 * OUT_DIM);
            asm volatile("cp.async.commit_group;");
            asm volatile("cp.async.wait_group 1;");
        } else {
            asm volatile("cp.async.wait_group 0;");
        }
        __syncthreads();
#pragma unroll
        for (int kk = 0; kk < 32; kk++) {
            float4 wv = *(const float4*)&Ws[cur][kk][4 * lane];
            float wvv[4] = {wv.x, wv.y, wv.z, wv.w};
            float av[4];
#pragma unroll
            for (int i = 0; i < 4; i++) av[i] = As[cur][wid + 8 * i][kk];
#pragma unroll
            for (int i = 0; i < 4; i++)
#pragma unroll
                for (int c = 0; c < 4; c++) acc[i][c] += av[i] * wvv[c];
        }
        __syncthreads();
    }

    float4 a2v = *(const float4*)&a2[4 * lane];
    float wmax = -1e30f;
#pragma unroll
    for (int i = 0; i < 4; i++) {
        int r = r0 + wid + 8 * i;
        float part = acc[i][0] * a2v.x + acc[i][1] * a2v.y +
                     acc[i][2] * a2v.z + acc[i][3] * a2v.w;
#pragma unroll
        for (int o = 16; o; o >>= 1) part += __shfl_xor_sync(0xffffffffu, part, o);
        if (lane == 0) {
            g_s2[r] = part;
            wmax = fmaxf(wmax, part);
        }
        // h row -> fp16 [n][f]
        __half2 h01 = __floats2half2_rn(acc[i][0], acc[i][1]);
        __half2 h23 = __floats2half2_rn(acc[i][2], acc[i][3]);
        __half2* dst = (__half2*)(g_hb + (size_t)r * OUT_DIM + 4 * lane);
        dst[0] = h01;
        dst[1] = h23;
    }
    if (lane == 0) atomicMax(&g_s2max_bits, f2key(wmax));
}

// ---------------- K2b: k_pq — p/q per n, P/Q per row (true S2max) ----------
__global__ __launch_bounds__(256) void k_pq() {
    const float M = key2f(g_s2max_bits);
    int idx = blockIdx.x * 256 + threadIdx.x;
    if (idx < N_COLS) {
        float d = g_s2[idx] - M;
        g_p[idx] = expf(d);
        g_q[idx] = expf(ALPHA * d);
    } else {
        int b = idx - N_COLS;                  // [0, B_ROWS)
        float s1 = -g_t[b];
        float v = s1 + M;
        float mh = fmaxf(v, ALPHA * v);        // leaky(v) >= row max of e
        g_P[b] = expf(v - mh);
        g_Q[b] = expf(ALPHA * v - mh);
    }
}

// ---------------- K3: k_main — HMMA weighted sum, RED into g_acc -----------
// CTA 256 thr, tile 128b x 128f, n-chunk 1024 in 32 K-tiles of 32.
// A = w [128 b][32 n] fp16 (gen in-kernel, rows 80B), ldmatrix non-trans.
// B = h [32 n][128 f] fp16 (cp.async from g_hb, rows 272B), ldmatrix.trans.
__global__ __launch_bounds__(256, 2) void k_main(const int* __restrict__ mask) {
    extern __shared__ __align__(16) char dsm[];
    const uint32_t sb = smem_u32(dsm);
    const uint32_t Wt[2] = {sb, sb + 10240};                         // 128*80
    const uint32_t Ht[3] = {sb + 20480, sb + 29184, sb + 37888};     // 32*272
    float* sT = (float*)(dsm + 46592);
    float* sP = sT + 128;
    float* sQ = sP + 128;

    const int tid = threadIdx.x, lane = tid & 31, wid = tid >> 5;
    const int qr = lane >> 2, qc = lane & 3;
    const int b0w = (wid >> 1) * 32, f0w = (wid & 1) * 64;
    const int gb0 = blockIdx.x * 128;
    const int nbase = blockIdx.y * NCHUNK;

    if (tid < 128) {
        sT[tid] = g_t[gb0 + tid];
        sP[tid] = g_P[gb0 + tid];
        sQ[tid] = g_Q[gb0 + tid];
    }

    // wgen mapping: warp -> 16 b rows, half-warp -> 8 rows, lane -> n-pair
    const int bsub = lane >> 4, np = lane & 15;
    const int bloc0 = wid * 16 + bsub * 8;
    const int* mrow = mask + (size_t)(gb0 + bloc0) * N_COLS + nbase + 2 * np;
    const uint32_t wg0 = (uint32_t)bloc0 * 80 + np * 4;

    // h cp.async mapping: row = tid>>3, two 16B chunks
    const int hrow = tid >> 3, hch = (tid & 7) * 2;
    const uint32_t hst = (uint32_t)hrow * 272 + hch * 16;
    const __half* hsrc = g_hb + (size_t)(nbase + hrow) * OUT_DIM + hch * 8;

    // ldmatrix per-lane row offsets
    const uint32_t lrow = (lane & 7) + ((lane >> 3) & 1) * 8;
    const uint32_t akoff = ((lane >> 4) & 1) * 16;
    const uint32_t arow_off = lrow * 80 + akoff;
    const uint32_t brow_off = lrow * 272 + akoff;

    // stage tile 0 + prefetch h tiles 0,1
    int2 mi[8];
    float2 pp, qq, ss;
#pragma unroll
    for (int i = 0; i < 8; i++) mi[i] = *(const int2*)(mrow + (size_t)i * N_COLS);
    {
        int n0 = nbase + 2 * np;
        pp = *(const float2*)&g_p[n0];
        qq = *(const float2*)&g_q[n0];
        ss = *(const float2*)&g_s2[n0];
    }
    cpa16(Ht[0] + hst, hsrc);
    cpa16(Ht[0] + hst + 16, hsrc + 8);
    asm volatile("cp.async.commit_group;");
    cpa16(Ht[1] + hst, hsrc + KT * OUT_DIM);
    cpa16(Ht[1] + hst + 16, hsrc + KT * OUT_DIM + 8);
    asm volatile("cp.async.commit_group;");

    float d[2][8][4];
#pragma unroll
    for (int mb = 0; mb < 2; mb++)
#pragma unroll
        for (int fb = 0; fb < 8; fb++)
#pragma unroll
            for (int c = 0; c < 4; c++) d[mb][fb][c] = 0.f;

    __syncthreads();  // sT/sP/sQ visible

    int hbi = 0;
    for (int t = 0; t < NT; t++) {
        const int wcur = t & 1;
        // generate w tile t (half2 per lane, 8 rows)
        {
            uint32_t wa = Wt[wcur] + wg0;
#pragma unroll
            for (int i = 0; i < 8; i++) {
                int b = bloc0 + i;
                float w0 = 0.f, w1 = 0.f;
                if (mi[i].x) w0 = (ss.x >= sT[b]) ? sP[b] * pp.x : sQ[b] * qq.x;
                if (mi[i].y) w1 = (ss.y >= sT[b]) ? sP[b] * pp.y : sQ[b] * qq.y;
                __half2 h2 = __floats2half2_rn(w0, w1);
                sts32(wa, *(uint32_t*)&h2);
                wa += 80;
            }
        }
        // stage tile t+1 (mask + n-scalars)
        if (t + 1 < NT) {
            const int* m2 = mrow + (t + 1) * KT;
#pragma unroll
            for (int i = 0; i < 8; i++) mi[i] = *(const int2*)(m2 + (size_t)i * N_COLS);
            int n0 = nbase + (t + 1) * KT + 2 * np;
            pp = *(const float2*)&g_p[n0];
            qq = *(const float2*)&g_q[n0];
            ss = *(const float2*)&g_s2[n0];
        }
        if (t + 1 < NT) asm volatile("cp.async.wait_group 1;");
        else            asm volatile("cp.async.wait_group 0;");
        __syncthreads();  // Wt[wcur] + Ht[hbi] ready; prior MMA complete

        // prefetch h tile t+2 (buffer freed by MMA(t-1) before last sync)
        if (t + 2 < NT) {
            int nb = (t + 2) % 3;
            const __half* src = hsrc + (t + 2) * KT * OUT_DIM;
            cpa16(Ht[nb] + hst, src);
            cpa16(Ht[nb] + hst + 16, src + 8);
            asm volatile("cp.async.commit_group;");
        }

        // MMA: 2j x (2 A-LDSM + 4 B-LDSM.trans + 16 HMMA)
#pragma unroll
        for (int j = 0; j < 2; j++) {
            uint32_t a[2][4];
            uint32_t abase = Wt[wcur] + b0w * 80 + j * 32 + arow_off;
            ldsm4(a[0], abase);
            ldsm4(a[1], abase + 1280);  // +16 rows
#pragma unroll
            for (int P = 0; P < 4; P++) {
                uint32_t b4[4];
                ldsm4t(b4, Ht[hbi] + j * 4352 + (f0w + P * 16) * 2 + brow_off);
                mma_f16(d[0][2 * P], a[0], b4[0], b4[1]);
                mma_f16(d[1][2 * P], a[1], b4[0], b4[1]);
                mma_f16(d[0][2 * P + 1], a[0], b4[2], b4[3]);
                mma_f16(d[1][2 * P + 1], a[1], b4[2], b4[3]);
            }
        }
        hbi = (hbi + 1) % 3;
    }

    // epilogue: atomic-reduce into g_acc
#pragma unroll
    for (int mb = 0; mb < 2; mb++) {
        int br = gb0 + b0w + mb * 16 + qr;
#pragma unroll
        for (int fb = 0; fb < 8; fb++) {
            int f = f0w + fb * 8 + qc * 2;
            float* p0 = g_acc + (size_t)br * OUT_DIM + f;
            redadd(p0, d[mb][fb][0]);
            redadd(p0 + 1, d[mb][fb][1]);
            redadd(p0 + 8 * OUT_DIM, d[mb][fb][2]);
            redadd(p0 + 8 * OUT_DIM + 1, d[mb][fb][3]);
        }
    }
}

// ---------------- K4: normalize ----------------
__global__ __launch_bounds__(128) void k_finish(float* __restrict__ out) {
    __shared__ float red[4];
    int b = blockIdx.x, f = threadIdx.x;
    float s = g_acc[(size_t)b * OUT_DIM + f];
    float ss = s * s;
#pragma unroll
    for (int o = 16; o; o >>= 1) ss += __shfl_xor_sync(0xffffffffu, ss, o);
    if ((f & 31) == 0) red[f >> 5] = ss;
    __syncthreads();
    float tot = red[0] + red[1] + red[2] + red[3];
    out[b * OUT_DIM + f] = s / fmaxf(sqrtf(tot), 1e-12f);
}

// ---------------- launch ----------------
extern "C" void kernel_launch(void* const* d_in, const int* in_sizes, int n_in,
                              void* d_out, int out_size) {
    const float* gf    = (const float*)d_in[0];  // [100000, 256]
    const int*   nodes = (const int*)d_in[1];    // [4096]
    const int*   un    = (const int*)d_in[2];    // [8192]
    const int*   mask  = (const int*)d_in[3];    // [4096, 8192]
    const float* W     = (const float*)d_in[4];  // [256, 128]
    const float* a1    = (const float*)d_in[5];  // [128]
    const float* a2    = (const float*)d_in[6];  // [128]
    float* out = (float*)d_out;                  // [4096, 128]

    static int smem_set = 0;
    const int SMEM = 46592 + 3 * 128 * 4;  // 2xWt + 3xHt + sT/sP/sQ = 48128
    if (!smem_set) {
        cudaFuncSetAttribute(k_main, cudaFuncAttributeMaxDynamicSharedMemorySize, SMEM);
        smem_set = 1;
    }

    k_prep<<<B_ROWS / 32, 256>>>(gf, nodes, W, a1);
    k_hneigh<<<N_COLS / 32, 256>>>(gf, un, W, a2);
    k_pq<<<(N_COLS + B_ROWS) / 256, 256>>>();
    k_main<<<dim3(B_ROWS / 128, NSPLIT), 256, SMEM>>>(mask);
    k_finish<<<B_ROWS, 128>>>(out);
}